// round 9
// baseline (speedup 1.0000x reference)
#include <cuda_runtime.h>
#include <cuda_bf16.h>
#include <cstdint>

#define NQ 2048
#define NK 4096
#define DIMK 1024

// Split-bf16 operand storage: per (pos, head) one 128B row = hi d0..31 | lo d0..31,
// 16B units permuted u ^= (pos & 7)  (conflict-free ldmatrix).
__device__ uint4 g_K_sw[NK * 8 * 8];   // (pos*8+head)*8 units
__device__ uint4 g_Q_sw[NQ * 8 * 8];

#define LDSM4(r, addr) \
    asm volatile("ldmatrix.sync.aligned.m8n8.x4.shared.b16 {%0,%1,%2,%3}, [%4];" \
        : "=r"((r)[0]),"=r"((r)[1]),"=r"((r)[2]),"=r"((r)[3]) : "r"(addr))

#define LDSM2(r, addr) \
    asm volatile("ldmatrix.sync.aligned.m8n8.x2.shared.b16 {%0,%1}, [%2];" \
        : "=r"((r)[0]),"=r"((r)[1]) : "r"(addr))

#define MMA_BF16(accp, a, b0, b1) \
    asm volatile("mma.sync.aligned.m16n8k16.row.col.f32.bf16.bf16.f32 " \
        "{%0,%1,%2,%3}, {%4,%5,%6,%7}, {%8,%9}, {%0,%1,%2,%3};" \
        : "+f"((accp)[0]),"+f"((accp)[1]),"+f"((accp)[2]),"+f"((accp)[3]) \
        : "r"((a)[0]),"r"((a)[1]),"r"((a)[2]),"r"((a)[3]), "r"(b0),"r"(b1))

static __device__ __forceinline__ uint32_t smem_u32(const void* p) {
    uint32_t a;
    asm("{ .reg .u64 t; cvta.to.shared.u64 t, %1; cvt.u32.u64 %0, t; }"
        : "=r"(a) : "l"(p));
    return a;
}

static __device__ __forceinline__ void split2(float f0, float f1,
                                              uint32_t& hv, uint32_t& lv) {
    __nv_bfloat16 h0 = __float2bfloat16(f0);
    __nv_bfloat16 h1 = __float2bfloat16(f1);
    __nv_bfloat16 l0 = __float2bfloat16(f0 - __bfloat162float(h0));
    __nv_bfloat16 l1 = __float2bfloat16(f1 - __bfloat162float(h1));
    hv = (uint32_t)__bfloat16_as_ushort(h0) | ((uint32_t)__bfloat16_as_ushort(h1) << 16);
    lv = (uint32_t)__bfloat16_as_ushort(l0) | ((uint32_t)__bfloat16_as_ushort(l1) << 16);
}

// ---------------------------------------------------------------------------
// Tensor-core projection (unchanged from R7): C[M,256] = A[M,1024] @ W^T.
// ---------------------------------------------------------------------------
__global__ __launch_bounds__(256, 2) void proj_mma(
    const float* __restrict__ Qin, const float* __restrict__ Kin,
    const float* __restrict__ Wq,  const float* __restrict__ Wk)
{
    __shared__ char smA[2][16384];   // 128 rows x 128B (hi32|lo32 bf16)
    __shared__ char smW[2][8192];    // 64 rows x 128B

    const int mtile = blockIdx.x >> 2;
    const int ntile = blockIdx.x & 3;
    const float* A; int isQ, m0;
    if (mtile < 16) { A = Qin; isQ = 1; m0 = mtile * 128; }
    else            { A = Kin; isQ = 0; m0 = (mtile - 16) * 128; }
    const float* W = isQ ? Wq : Wk;
    const int n0 = ntile * 64;

    const int tid  = threadIdx.x;
    const int wid  = tid >> 5;
    const int lane = tid & 31;
    const int wm = wid >> 1;
    const int wn = wid & 1;

    const int lrow = tid >> 3;
    const int fc   = tid & 7;
    const float* aBase = A + (size_t)(m0 + lrow) * DIMK + fc * 4;
    const float* wBase = W + (size_t)(n0 + lrow) * DIMK + fc * 4;
    const int r7L  = lrow & 7;
    const int hiOff = (((fc >> 1) ^ r7L) << 4) + (fc & 1) * 8;
    const int loOff = ((((fc >> 1) + 4) ^ r7L) << 4) + (fc & 1) * 8;

    const uint32_t smA_u = smem_u32(smA);
    const uint32_t smW_u = smem_u32(smW);

    float4 pa[4], pw[2];
#pragma unroll
    for (int p = 0; p < 4; p++) pa[p] = *(const float4*)(aBase + p * 32 * DIMK);
#pragma unroll
    for (int p = 0; p < 2; p++) pw[p] = *(const float4*)(wBase + p * 32 * DIMK);

#pragma unroll
    for (int p = 0; p < 4; p++) {
        uint32_t h0, l0, h1, l1;
        split2(pa[p].x, pa[p].y, h0, l0);
        split2(pa[p].z, pa[p].w, h1, l1);
        char* rb = smA[0] + (lrow + p * 32) * 128;
        *(uint2*)(rb + hiOff) = make_uint2(h0, h1);
        *(uint2*)(rb + loOff) = make_uint2(l0, l1);
    }
#pragma unroll
    for (int p = 0; p < 2; p++) {
        uint32_t h0, l0, h1, l1;
        split2(pw[p].x, pw[p].y, h0, l0);
        split2(pw[p].z, pw[p].w, h1, l1);
        char* rb = smW[0] + (lrow + p * 32) * 128;
        *(uint2*)(rb + hiOff) = make_uint2(h0, h1);
        *(uint2*)(rb + loOff) = make_uint2(l0, l1);
    }
    __syncthreads();

    const int rowA0 = wm * 32 + (lane & 7) + ((lane >> 3) & 1) * 8;
    const int uaddA = (lane >> 4) & 1;
    const int rowB0 = wn * 32 + (lane & 7) + ((lane >> 4) & 1) * 8;
    const int uaddB = (lane >> 3) & 1;
    const int ar7_0 = rowA0 & 7;
    const int br7_0 = rowB0 & 7;

    float acc[2][4][4];
#pragma unroll
    for (int mm = 0; mm < 2; mm++)
#pragma unroll
        for (int nn = 0; nn < 4; nn++)
#pragma unroll
            for (int c = 0; c < 4; c++) acc[mm][nn][c] = 0.f;

    for (int ch = 0; ch < 32; ch++) {
        const int buf = ch & 1;
        if (ch < 31) {
            const int kc = (ch + 1) * 32;
#pragma unroll
            for (int p = 0; p < 4; p++) pa[p] = *(const float4*)(aBase + p * 32 * DIMK + kc);
#pragma unroll
            for (int p = 0; p < 2; p++) pw[p] = *(const float4*)(wBase + p * 32 * DIMK + kc);
        }

        const uint32_t aB = smA_u + buf * 16384;
        const uint32_t bB = smW_u + buf * 8192;
#pragma unroll
        for (int s = 0; s < 2; s++) {
            const int uHA = s * 2 + uaddA, uLA = uHA + 4;
            const int uHB = s * 2 + uaddB, uLB = uHB + 4;
            uint32_t aH0[4], aH1[4], aL0[4], aL1[4];
            uint32_t bH0[4], bH1[4], bL0[4], bL1[4];
            LDSM4(aH0, aB + rowA0 * 128        + ((uHA ^ ar7_0) << 4));
            LDSM4(aH1, aB + (rowA0 + 16) * 128 + ((uHA ^ ar7_0) << 4));
            LDSM4(bH0, bB + rowB0 * 128        + ((uHB ^ br7_0) << 4));
            LDSM4(bH1, bB + (rowB0 + 16) * 128 + ((uHB ^ br7_0) << 4));
            LDSM4(aL0, aB + rowA0 * 128        + ((uLA ^ ar7_0) << 4));
            LDSM4(aL1, aB + (rowA0 + 16) * 128 + ((uLA ^ ar7_0) << 4));
            LDSM4(bL0, bB + rowB0 * 128        + ((uLB ^ br7_0) << 4));
            LDSM4(bL1, bB + (rowB0 + 16) * 128 + ((uLB ^ br7_0) << 4));

            MMA_BF16(acc[0][0], aH0, bH0[0], bH0[1]); MMA_BF16(acc[0][1], aH0, bH0[2], bH0[3]);
            MMA_BF16(acc[0][2], aH0, bH1[0], bH1[1]); MMA_BF16(acc[0][3], aH0, bH1[2], bH1[3]);
            MMA_BF16(acc[1][0], aH1, bH0[0], bH0[1]); MMA_BF16(acc[1][1], aH1, bH0[2], bH0[3]);
            MMA_BF16(acc[1][2], aH1, bH1[0], bH1[1]); MMA_BF16(acc[1][3], aH1, bH1[2], bH1[3]);

            MMA_BF16(acc[0][0], aH0, bL0[0], bL0[1]); MMA_BF16(acc[0][1], aH0, bL0[2], bL0[3]);
            MMA_BF16(acc[0][2], aH0, bL1[0], bL1[1]); MMA_BF16(acc[0][3], aH0, bL1[2], bL1[3]);
            MMA_BF16(acc[1][0], aH1, bL0[0], bL0[1]); MMA_BF16(acc[1][1], aH1, bL0[2], bL0[3]);
            MMA_BF16(acc[1][2], aH1, bL1[0], bL1[1]); MMA_BF16(acc[1][3], aH1, bL1[2], bL1[3]);

            MMA_BF16(acc[0][0], aL0, bH0[0], bH0[1]); MMA_BF16(acc[0][1], aL0, bH0[2], bH0[3]);
            MMA_BF16(acc[0][2], aL0, bH1[0], bH1[1]); MMA_BF16(acc[0][3], aL0, bH1[2], bH1[3]);
            MMA_BF16(acc[1][0], aL1, bH0[0], bH0[1]); MMA_BF16(acc[1][1], aL1, bH0[2], bH0[3]);
            MMA_BF16(acc[1][2], aL1, bH1[0], bH1[1]); MMA_BF16(acc[1][3], aL1, bH1[2], bH1[3]);
        }
        __syncthreads();

        if (ch < 31) {
            const int nb = 1 - buf;
#pragma unroll
            for (int p = 0; p < 4; p++) {
                uint32_t h0, l0, h1, l1;
                split2(pa[p].x, pa[p].y, h0, l0);
                split2(pa[p].z, pa[p].w, h1, l1);
                char* rb = smA[nb] + (lrow + p * 32) * 128;
                *(uint2*)(rb + hiOff) = make_uint2(h0, h1);
                *(uint2*)(rb + loOff) = make_uint2(l0, l1);
            }
#pragma unroll
            for (int p = 0; p < 2; p++) {
                uint32_t h0, l0, h1, l1;
                split2(pw[p].x, pw[p].y, h0, l0);
                split2(pw[p].z, pw[p].w, h1, l1);
                char* rb = smW[nb] + (lrow + p * 32) * 128;
                *(uint2*)(rb + hiOff) = make_uint2(h0, h1);
                *(uint2*)(rb + loOff) = make_uint2(l0, l1);
            }
            __syncthreads();
        }
    }

    unsigned char* gbase = (unsigned char*)(isQ ? g_Q_sw : g_K_sw);
#pragma unroll
    for (int mm = 0; mm < 2; mm++) {
#pragma unroll
        for (int nn = 0; nn < 4; nn++) {
            const int n = n0 + wn * 32 + nn * 8 + (lane & 3) * 2;
            const int head = n >> 5;
            const int d0 = n & 31;
            const int u = d0 >> 3;
            const int within = (d0 & 7) * 2;
#pragma unroll
            for (int rr = 0; rr < 2; rr++) {
                const int m = m0 + wm * 32 + mm * 16 + (lane >> 2) + rr * 8;
                uint32_t hv, lv;
                split2(acc[mm][nn][rr * 2], acc[mm][nn][rr * 2 + 1], hv, lv);
                unsigned char* rb = gbase + (size_t)(m * 8 + head) * 128;
                const int r7 = m & 7;
                *(uint32_t*)(rb + ((u ^ r7) << 4) + within)       = hv;
                *(uint32_t*)(rb + (((u + 4) ^ r7) << 4) + within) = lv;
            }
        }
    }
}

// ---------------------------------------------------------------------------
// Main kernel: CTA 32k x 32q, 8 warps (2k x 4q), warp tile 16k x 8q, 8 heads.
// acc = 32 regs/thread; 3 CTAs/SM target via launch_bounds + 69.9KB smem.
// ---------------------------------------------------------------------------
#define SM_K    0          // 32 rows * 1KB = 32768
#define SM_Q    32768      // 32768
#define SM_RPE  65536      // 257 * 16B = 4112
#define SM_QP   69648      // 32 * 4B
#define SM_KP   69776      // 32 * 4B
#define SM_TOT  69904

__global__ __launch_bounds__(256, 3) void rpe_gate_mma(
    const int*   __restrict__ qpos, const int* __restrict__ kpos,
    const float* __restrict__ rpe_table,
    const float* __restrict__ w1, const float* __restrict__ b1,
    const float* __restrict__ w2, const float* __restrict__ b2,
    float* __restrict__ out)
{
    extern __shared__ char sm[];
    const uint32_t sb = smem_u32(sm);

    const int tid  = threadIdx.x;
    const int wid  = tid >> 5;
    const int lane = tid & 31;
    const int ktile = blockIdx.x;   // 32 k rows
    const int qtile = blockIdx.y;   // 32 q cols

    {
        const uint4* srcK = g_K_sw + (size_t)ktile * 2048;
        const uint4* srcQ = g_Q_sw + (size_t)qtile * 2048;
#pragma unroll
        for (int i = 0; i < 8; i++) {
            int u = tid + i * 256;
            asm volatile("cp.async.cg.shared.global [%0], [%1], 16;"
                :: "r"(sb + SM_K + u * 16), "l"(srcK + u) : "memory");
        }
#pragma unroll
        for (int i = 0; i < 8; i++) {
            int u = tid + i * 256;
            asm volatile("cp.async.cg.shared.global [%0], [%1], 16;"
                :: "r"(sb + SM_Q + u * 16), "l"(srcQ + u) : "memory");
        }
        asm volatile("cp.async.commit_group;");
    }
    for (int i = tid; i < 257; i += 256)
        *(float4*)(sm + SM_RPE + i * 16) = ((const float4*)rpe_table)[i];
    if (tid < 32) *(int*)(sm + SM_QP + tid * 4) = qpos[qtile * 32 + tid];
    if (tid >= 32 && tid < 64)
        *(int*)(sm + SM_KP + (tid - 32) * 4) = kpos[ktile * 32 + (tid - 32)];

    asm volatile("cp.async.wait_group 0;");
    __syncthreads();

    const int wk0 = (wid & 1) * 16;
    const int wq0 = (wid >> 1) * 8;

    const int rowA = wk0 + (lane & 7) + ((lane >> 3) & 1) * 8;
    const int uaddA = (lane >> 4) & 1;
    const int rowB = wq0 + (lane & 7);
    const int uaddB = (lane >> 3) & 1;
    const uint32_t aRow = sb + SM_K + rowA * 1024;
    const uint32_t bRow = sb + SM_Q + rowB * 1024;
    const int ar7 = rowA & 7;
    const int br7 = rowB & 7;

    float acc[8][4];
#pragma unroll
    for (int h = 0; h < 8; h++)
#pragma unroll
        for (int c = 0; c < 4; c++) acc[h][c] = 0.f;

#pragma unroll
    for (int h = 0; h < 8; h++) {
        const uint32_t ah = aRow + h * 128;
        const uint32_t bh = bRow + h * 128;
#pragma unroll
        for (int s = 0; s < 2; s++) {
            const int uHA = s * 2 + uaddA, uLA = uHA + 4;
            const int uHB = s * 2 + uaddB, uLB = uHB + 4;
            uint32_t aH[4], aL[4], bH[2], bL[2];
            LDSM4(aH, ah + ((uHA ^ ar7) << 4));
            LDSM2(bH, bh + ((uHB ^ br7) << 4));
            LDSM4(aL, ah + ((uLA ^ ar7) << 4));
            LDSM2(bL, bh + ((uLB ^ br7) << 4));
            MMA_BF16(acc[h], aH, bH[0], bH[1]);
            MMA_BF16(acc[h], aH, bL[0], bL[1]);
            MMA_BF16(acc[h], aL, bH[0], bH[1]);
        }
    }

    // ---- Epilogue (weights via __ldg, loaded post-MMA) ----
    float w1r[8][4], b1r[8], w2r[4][8], b2r[4];
#pragma unroll
    for (int e = 0; e < 8; e++) {
        b1r[e] = __ldg(&b1[e]);
#pragma unroll
        for (int h = 0; h < 4; h++) w1r[e][h] = __ldg(&w1[e * 4 + h]);
    }
#pragma unroll
    for (int h = 0; h < 4; h++) {
        b2r[h] = __ldg(&b2[h]);
#pragma unroll
        for (int e = 0; e < 8; e++) w2r[h][e] = __ldg(&w2[h * 8 + e]);
    }

    const float4* rpe_s = (const float4*)(sm + SM_RPE);
    const int* qp_s = (const int*)(sm + SM_QP);
    const int* kp_s = (const int*)(sm + SM_KP);

    const int krow0 = wk0 + (lane >> 2);
    const int qcol0 = wq0 + (lane & 3) * 2;
    const int kg0 = ktile * 32;
    const int qg0 = qtile * 32;

    int kv[2], qv[2];
#pragma unroll
    for (int kr = 0; kr < 2; kr++) kv[kr] = kp_s[krow0 + kr * 8];
#pragma unroll
    for (int qc = 0; qc < 2; qc++) qv[qc] = qp_s[qcol0 + qc];

#pragma unroll
    for (int kr = 0; kr < 2; kr++) {
#pragma unroll
        for (int qc = 0; qc < 2; qc++) {
            const int c = kr * 2 + qc;
            int rel = qv[qc] - kv[kr];
            rel = rel < -128 ? -128 : (rel > 128 ? 128 : rel);
            float4 rp = rpe_s[rel + 128];
            float rph[4] = {rp.x, rp.y, rp.z, rp.w};

            float sh[4], gh[4];
#pragma unroll
            for (int h = 0; h < 4; h++) {
                sh[h] = fmaxf(acc[h][c] + rph[h], 0.f);
                gh[h] = acc[4 + h][c] + rph[h];
            }
            float zh[4] = {b2r[0], b2r[1], b2r[2], b2r[3]};
#pragma unroll
            for (int e = 0; e < 8; e++) {
                float t = b1r[e];
#pragma unroll
                for (int h = 0; h < 4; h++) t = fmaf(gh[h], w1r[e][h], t);
                t = fmaxf(t, 0.f);
#pragma unroll
                for (int h = 0; h < 4; h++) zh[h] = fmaf(t, w2r[h][e], zh[h]);
            }
            float o = 0.f;
#pragma unroll
            for (int h = 0; h < 4; h++) {
                float g = __fdividef(1.f, 1.f + __expf(-zh[h]));
                o = fmaf(sh[h], g, o);
            }
            const int qg = qg0 + qcol0 + qc;
            const int kg = kg0 + krow0 + kr * 8;
            out[(size_t)qg * NK + kg] = o;
        }
    }
}

// ---------------------------------------------------------------------------
extern "C" void kernel_launch(void* const* d_in, const int* in_sizes, int n_in,
                              void* d_out, int out_size)
{
    const float* query = (const float*)d_in[0];
    const float* key   = (const float*)d_in[1];
    const int*   qpos  = (const int*)  d_in[2];
    const int*   kpos  = (const int*)  d_in[3];
    const float* Wq    = (const float*)d_in[4];
    const float* Wk    = (const float*)d_in[5];
    const float* rpe   = (const float*)d_in[6];
    const float* w1    = (const float*)d_in[7];
    const float* b1    = (const float*)d_in[8];
    const float* w2    = (const float*)d_in[9];
    const float* b2    = (const float*)d_in[10];
    float* out = (float*)d_out;
    (void)in_sizes; (void)n_in; (void)out_size;

    cudaFuncSetAttribute(rpe_gate_mma,
                         cudaFuncAttributeMaxDynamicSharedMemorySize, SM_TOT);

    proj_mma<<<192, 256>>>(query, key, Wq, Wk);
    rpe_gate_mma<<<dim3(NK / 32, NQ / 32), 256, SM_TOT>>>(
        qpos, kpos, rpe, w1, b1, w2, b2, out);
}

// round 10
// speedup vs baseline: 1.4017x; 1.4017x over previous
#include <cuda_runtime.h>
#include <cuda_bf16.h>
#include <cstdint>

#define NQ 2048
#define NK 4096
#define DIMK 1024

// Split-bf16 operand storage: per (pos, head) one 128B row = hi d0..31 | lo d0..31,
// 16B units permuted u ^= (pos & 7)  (conflict-free ldmatrix).
__device__ uint4 g_K_sw[NK * 8 * 8];   // (pos*8+head)*8 units
__device__ uint4 g_Q_sw[NQ * 8 * 8];

#define LDSM4(r, addr) \
    asm volatile("ldmatrix.sync.aligned.m8n8.x4.shared.b16 {%0,%1,%2,%3}, [%4];" \
        : "=r"((r)[0]),"=r"((r)[1]),"=r"((r)[2]),"=r"((r)[3]) : "r"(addr))

#define MMA_BF16(accp, a, b0, b1) \
    asm volatile("mma.sync.aligned.m16n8k16.row.col.f32.bf16.bf16.f32 " \
        "{%0,%1,%2,%3}, {%4,%5,%6,%7}, {%8,%9}, {%0,%1,%2,%3};" \
        : "+f"((accp)[0]),"+f"((accp)[1]),"+f"((accp)[2]),"+f"((accp)[3]) \
        : "r"((a)[0]),"r"((a)[1]),"r"((a)[2]),"r"((a)[3]), "r"(b0),"r"(b1))

static __device__ __forceinline__ uint32_t smem_u32(const void* p) {
    uint32_t a;
    asm("{ .reg .u64 t; cvta.to.shared.u64 t, %1; cvt.u32.u64 %0, t; }"
        : "=r"(a) : "l"(p));
    return a;
}

static __device__ __forceinline__ void split2(float f0, float f1,
                                              uint32_t& hv, uint32_t& lv) {
    __nv_bfloat16 h0 = __float2bfloat16(f0);
    __nv_bfloat16 h1 = __float2bfloat16(f1);
    __nv_bfloat16 l0 = __float2bfloat16(f0 - __bfloat162float(h0));
    __nv_bfloat16 l1 = __float2bfloat16(f1 - __bfloat162float(h1));
    hv = (uint32_t)__bfloat16_as_ushort(h0) | ((uint32_t)__bfloat16_as_ushort(h1) << 16);
    lv = (uint32_t)__bfloat16_as_ushort(l0) | ((uint32_t)__bfloat16_as_ushort(l1) << 16);
}

// ---------------------------------------------------------------------------
// Tensor-core projection, re-tiled for occupancy: CTA 64M x 64N, 8 warps
// (2m x 4n), warp 32x16, K-chunk 32, double-buffered (32KB smem).
// Grid: 96 m-tiles (32 Q + 64 K) x 4 n-tiles = 384 CTAs, 3 CTAs/SM target.
// ---------------------------------------------------------------------------
__global__ __launch_bounds__(256, 3) void proj_mma(
    const float* __restrict__ Qin, const float* __restrict__ Kin,
    const float* __restrict__ Wq,  const float* __restrict__ Wk)
{
    __shared__ char smA[2][8192];   // 64 rows x 128B (hi32|lo32 bf16)
    __shared__ char smW[2][8192];   // 64 rows x 128B

    const int mtile = blockIdx.x >> 2;     // 0..95
    const int ntile = blockIdx.x & 3;
    const float* A; int isQ, m0;
    if (mtile < 32) { A = Qin; isQ = 1; m0 = mtile * 64; }
    else            { A = Kin; isQ = 0; m0 = (mtile - 32) * 64; }
    const float* W = isQ ? Wq : Wk;
    const int n0 = ntile * 64;

    const int tid  = threadIdx.x;
    const int wid  = tid >> 5;
    const int lane = tid & 31;
    const int wm = wid & 1;       // m sub (32 rows)
    const int wn = wid >> 1;      // n sub (16 cols)

    // ---- load/convert thread mapping: 32 rows per pass, 2 passes ----
    const int lrow = tid >> 3;        // 0..31
    const int fc   = tid & 7;         // float4 col (d0 = fc*4)
    const float* aBase = A + (size_t)(m0 + lrow) * DIMK + fc * 4;
    const float* wBase = W + (size_t)(n0 + lrow) * DIMK + fc * 4;
    const int r7L  = lrow & 7;        // (lrow+32)&7 == lrow&7
    const int hiOff = (((fc >> 1) ^ r7L) << 4) + (fc & 1) * 8;
    const int loOff = ((((fc >> 1) + 4) ^ r7L) << 4) + (fc & 1) * 8;

    const uint32_t smA_u = smem_u32(smA);
    const uint32_t smW_u = smem_u32(smW);

    float4 pa[2], pw[2];
#pragma unroll
    for (int p = 0; p < 2; p++) {
        pa[p] = *(const float4*)(aBase + p * 32 * DIMK);
        pw[p] = *(const float4*)(wBase + p * 32 * DIMK);
    }

    // store chunk 0 into buf 0
#pragma unroll
    for (int p = 0; p < 2; p++) {
        uint32_t h0, l0, h1, l1;
        split2(pa[p].x, pa[p].y, h0, l0);
        split2(pa[p].z, pa[p].w, h1, l1);
        char* rb = smA[0] + (lrow + p * 32) * 128;
        *(uint2*)(rb + hiOff) = make_uint2(h0, h1);
        *(uint2*)(rb + loOff) = make_uint2(l0, l1);
        split2(pw[p].x, pw[p].y, h0, l0);
        split2(pw[p].z, pw[p].w, h1, l1);
        rb = smW[0] + (lrow + p * 32) * 128;
        *(uint2*)(rb + hiOff) = make_uint2(h0, h1);
        *(uint2*)(rb + loOff) = make_uint2(l0, l1);
    }
    __syncthreads();

    // ---- ldmatrix per-thread address components ----
    // A (rows = m): x4 covers 16 rows x 16 cols per ldsm; mm adds +16 rows.
    const int rowA0 = wm * 32 + (lane & 7) + ((lane >> 3) & 1) * 8;
    const int uaddA = (lane >> 4) & 1;
    // B (rows = n, 16 per warp): x4 covers both 8-col groups (R7-main pattern).
    const int rowB0 = wn * 16 + (lane & 7) + ((lane >> 4) & 1) * 8;
    const int uaddB = (lane >> 3) & 1;
    const int ar7 = rowA0 & 7;
    const int br7 = rowB0 & 7;

    float acc[2][2][4];
#pragma unroll
    for (int mm = 0; mm < 2; mm++)
#pragma unroll
        for (int nn = 0; nn < 2; nn++)
#pragma unroll
            for (int c = 0; c < 4; c++) acc[mm][nn][c] = 0.f;

    for (int ch = 0; ch < 32; ch++) {
        const int buf = ch & 1;
        if (ch < 31) {
            const int kc = (ch + 1) * 32;
#pragma unroll
            for (int p = 0; p < 2; p++) {
                pa[p] = *(const float4*)(aBase + p * 32 * DIMK + kc);
                pw[p] = *(const float4*)(wBase + p * 32 * DIMK + kc);
            }
        }

        const uint32_t aB = smA_u + buf * 8192;
        const uint32_t bB = smW_u + buf * 8192;
#pragma unroll
        for (int s = 0; s < 2; s++) {
            const int uHA = s * 2 + uaddA, uLA = uHA + 4;
            const int uHB = s * 2 + uaddB, uLB = uHB + 4;
            uint32_t aH0[4], aH1[4], aL0[4], aL1[4], bH[4], bL[4];
            LDSM4(aH0, aB + rowA0 * 128        + ((uHA ^ ar7) << 4));
            LDSM4(aH1, aB + (rowA0 + 16) * 128 + ((uHA ^ ar7) << 4));
            LDSM4(bH,  bB + rowB0 * 128        + ((uHB ^ br7) << 4));
            LDSM4(aL0, aB + rowA0 * 128        + ((uLA ^ ar7) << 4));
            LDSM4(aL1, aB + (rowA0 + 16) * 128 + ((uLA ^ ar7) << 4));
            LDSM4(bL,  bB + rowB0 * 128        + ((uLB ^ br7) << 4));

            // hi*hi
            MMA_BF16(acc[0][0], aH0, bH[0], bH[1]); MMA_BF16(acc[0][1], aH0, bH[2], bH[3]);
            MMA_BF16(acc[1][0], aH1, bH[0], bH[1]); MMA_BF16(acc[1][1], aH1, bH[2], bH[3]);
            // hi*lo
            MMA_BF16(acc[0][0], aH0, bL[0], bL[1]); MMA_BF16(acc[0][1], aH0, bL[2], bL[3]);
            MMA_BF16(acc[1][0], aH1, bL[0], bL[1]); MMA_BF16(acc[1][1], aH1, bL[2], bL[3]);
            // lo*hi
            MMA_BF16(acc[0][0], aL0, bH[0], bH[1]); MMA_BF16(acc[0][1], aL0, bH[2], bH[3]);
            MMA_BF16(acc[1][0], aL1, bH[0], bH[1]); MMA_BF16(acc[1][1], aL1, bH[2], bH[3]);
        }
        __syncthreads();

        if (ch < 31) {
            const int nb = 1 - buf;
#pragma unroll
            for (int p = 0; p < 2; p++) {
                uint32_t h0, l0, h1, l1;
                split2(pa[p].x, pa[p].y, h0, l0);
                split2(pa[p].z, pa[p].w, h1, l1);
                char* rb = smA[nb] + (lrow + p * 32) * 128;
                *(uint2*)(rb + hiOff) = make_uint2(h0, h1);
                *(uint2*)(rb + loOff) = make_uint2(l0, l1);
                split2(pw[p].x, pw[p].y, h0, l0);
                split2(pw[p].z, pw[p].w, h1, l1);
                rb = smW[nb] + (lrow + p * 32) * 128;
                *(uint2*)(rb + hiOff) = make_uint2(h0, h1);
                *(uint2*)(rb + loOff) = make_uint2(l0, l1);
            }
            __syncthreads();
        }
    }

    // ---- Epilogue: fp32 -> bf16 split, write swizzled global layout ----
    unsigned char* gbase = (unsigned char*)(isQ ? g_Q_sw : g_K_sw);
#pragma unroll
    for (int mm = 0; mm < 2; mm++) {
#pragma unroll
        for (int nn = 0; nn < 2; nn++) {
            const int n = n0 + wn * 16 + nn * 8 + (lane & 3) * 2;
            const int head = n >> 5;
            const int d0 = n & 31;
            const int u = d0 >> 3;
            const int within = (d0 & 7) * 2;
#pragma unroll
            for (int rr = 0; rr < 2; rr++) {
                const int m = m0 + wm * 32 + mm * 16 + (lane >> 2) + rr * 8;
                uint32_t hv, lv;
                split2(acc[mm][nn][rr * 2], acc[mm][nn][rr * 2 + 1], hv, lv);
                unsigned char* rb = gbase + (size_t)(m * 8 + head) * 128;
                const int r7 = m & 7;
                *(uint32_t*)(rb + ((u ^ r7) << 4) + within)       = hv;
                *(uint32_t*)(rb + (((u + 4) ^ r7) << 4) + within) = lv;
            }
        }
    }
}

// ---------------------------------------------------------------------------
// Main kernel (exact R7 config): CTA 64k x 32q, 8 warps, warp 16k x 16q.
// ---------------------------------------------------------------------------
#define SM_K    0
#define SM_Q    65536
#define SM_RPE  98304
#define SM_QP   102416
#define SM_KP   102544
#define SM_TOT  102800

__global__ __launch_bounds__(256) void rpe_gate_mma(
    const int*   __restrict__ qpos, const int* __restrict__ kpos,
    const float* __restrict__ rpe_table,
    const float* __restrict__ w1, const float* __restrict__ b1,
    const float* __restrict__ w2, const float* __restrict__ b2,
    float* __restrict__ out)
{
    extern __shared__ char sm[];
    const uint32_t sb = smem_u32(sm);

    const int tid  = threadIdx.x;
    const int wid  = tid >> 5;
    const int lane = tid & 31;
    const int ktile = blockIdx.x;
    const int qtile = blockIdx.y;

    {
        const uint4* srcK = g_K_sw + (size_t)ktile * 4096;
        const uint4* srcQ = g_Q_sw + (size_t)qtile * 2048;
#pragma unroll
        for (int i = 0; i < 16; i++) {
            int u = tid + i * 256;
            asm volatile("cp.async.cg.shared.global [%0], [%1], 16;"
                :: "r"(sb + SM_K + u * 16), "l"(srcK + u) : "memory");
        }
#pragma unroll
        for (int i = 0; i < 8; i++) {
            int u = tid + i * 256;
            asm volatile("cp.async.cg.shared.global [%0], [%1], 16;"
                :: "r"(sb + SM_Q + u * 16), "l"(srcQ + u) : "memory");
        }
        asm volatile("cp.async.commit_group;");
    }
    for (int i = tid; i < 257; i += 256)
        *(float4*)(sm + SM_RPE + i * 16) = ((const float4*)rpe_table)[i];
    if (tid < 32) *(int*)(sm + SM_QP + tid * 4) = qpos[qtile * 32 + tid];
    if (tid < 64) *(int*)(sm + SM_KP + tid * 4) = kpos[ktile * 64 + tid];

    asm volatile("cp.async.wait_group 0;");
    __syncthreads();

    const int wk0 = (wid & 3) * 16;
    const int wq0 = (wid >> 2) * 16;

    const int rowA = wk0 + (lane & 7) + ((lane >> 3) & 1) * 8;
    const int uaddA = (lane >> 4) & 1;
    const int rowB = wq0 + (lane & 7) + ((lane >> 4) & 1) * 8;
    const int uaddB = (lane >> 3) & 1;
    const uint32_t aRow = sb + SM_K + rowA * 1024;
    const uint32_t bRow = sb + SM_Q + rowB * 1024;
    const int ar7 = rowA & 7;
    const int br7 = rowB & 7;

    float acc[8][2][4];
#pragma unroll
    for (int h = 0; h < 8; h++)
#pragma unroll
        for (int j = 0; j < 2; j++)
#pragma unroll
            for (int c = 0; c < 4; c++) acc[h][j][c] = 0.f;

#pragma unroll
    for (int h = 0; h < 8; h++) {
        const uint32_t ah = aRow + h * 128;
        const uint32_t bh = bRow + h * 128;
#pragma unroll
        for (int s = 0; s < 2; s++) {
            const int uHiA = s * 2 + uaddA, uLoA = uHiA + 4;
            const int uHiB = s * 2 + uaddB, uLoB = uHiB + 4;
            uint32_t aH[4], aL[4], bH[4], bL[4];
            LDSM4(aH, ah + ((uHiA ^ ar7) << 4));
            LDSM4(bH, bh + ((uHiB ^ br7) << 4));
            LDSM4(aL, ah + ((uLoA ^ ar7) << 4));
            LDSM4(bL, bh + ((uLoB ^ br7) << 4));
            MMA_BF16(acc[h][0], aH, bH[0], bH[1]);
            MMA_BF16(acc[h][1], aH, bH[2], bH[3]);
            MMA_BF16(acc[h][0], aH, bL[0], bL[1]);
            MMA_BF16(acc[h][1], aH, bL[2], bL[3]);
            MMA_BF16(acc[h][0], aL, bH[0], bH[1]);
            MMA_BF16(acc[h][1], aL, bH[2], bH[3]);
        }
    }

    float w1r[8][4], b1r[8], w2r[4][8], b2r[4];
#pragma unroll
    for (int e = 0; e < 8; e++) {
        b1r[e] = __ldg(&b1[e]);
#pragma unroll
        for (int h = 0; h < 4; h++) w1r[e][h] = __ldg(&w1[e * 4 + h]);
    }
#pragma unroll
    for (int h = 0; h < 4; h++) {
        b2r[h] = __ldg(&b2[h]);
#pragma unroll
        for (int e = 0; e < 8; e++) w2r[h][e] = __ldg(&w2[h * 8 + e]);
    }

    const float4* rpe_s = (const float4*)(sm + SM_RPE);
    const int* qp_s = (const int*)(sm + SM_QP);
    const int* kp_s = (const int*)(sm + SM_KP);

    const int krow0 = wk0 + (lane >> 2);
    const int qcol0 = wq0 + (lane & 3) * 2;
    const int kg0 = ktile * 64;
    const int qg0 = qtile * 32;

    int kv[2], qv[2][2];
#pragma unroll
    for (int kr = 0; kr < 2; kr++) kv[kr] = kp_s[krow0 + kr * 8];
#pragma unroll
    for (int j = 0; j < 2; j++)
#pragma unroll
        for (int qc = 0; qc < 2; qc++) qv[j][qc] = qp_s[qcol0 + j * 8 + qc];

#pragma unroll
    for (int j = 0; j < 2; j++) {
#pragma unroll
        for (int kr = 0; kr < 2; kr++) {
#pragma unroll
            for (int qc = 0; qc < 2; qc++) {
                const int c = kr * 2 + qc;
                int rel = qv[j][qc] - kv[kr];
                rel = rel < -128 ? -128 : (rel > 128 ? 128 : rel);
                float4 rp = rpe_s[rel + 128];
                float rph[4] = {rp.x, rp.y, rp.z, rp.w};

                float sh[4], gh[4];
#pragma unroll
                for (int h = 0; h < 4; h++) {
                    sh[h] = fmaxf(acc[h][j][c] + rph[h], 0.f);
                    gh[h] = acc[4 + h][j][c] + rph[h];
                }
                float zh[4] = {b2r[0], b2r[1], b2r[2], b2r[3]};
#pragma unroll
                for (int e = 0; e < 8; e++) {
                    float t = b1r[e];
#pragma unroll
                    for (int h = 0; h < 4; h++) t = fmaf(gh[h], w1r[e][h], t);
                    t = fmaxf(t, 0.f);
#pragma unroll
                    for (int h = 0; h < 4; h++) zh[h] = fmaf(t, w2r[h][e], zh[h]);
                }
                float o = 0.f;
#pragma unroll
                for (int h = 0; h < 4; h++) {
                    float g = __fdividef(1.f, 1.f + __expf(-zh[h]));
                    o = fmaf(sh[h], g, o);
                }
                const int qg = qg0 + qcol0 + j * 8 + qc;
                const int kg = kg0 + krow0 + kr * 8;
                out[(size_t)qg * NK + kg] = o;
            }
        }
    }
}

// ---------------------------------------------------------------------------
extern "C" void kernel_launch(void* const* d_in, const int* in_sizes, int n_in,
                              void* d_out, int out_size)
{
    const float* query = (const float*)d_in[0];
    const float* key   = (const float*)d_in[1];
    const int*   qpos  = (const int*)  d_in[2];
    const int*   kpos  = (const int*)  d_in[3];
    const float* Wq    = (const float*)d_in[4];
    const float* Wk    = (const float*)d_in[5];
    const float* rpe   = (const float*)d_in[6];
    const float* w1    = (const float*)d_in[7];
    const float* b1    = (const float*)d_in[8];
    const float* w2    = (const float*)d_in[9];
    const float* b2    = (const float*)d_in[10];
    float* out = (float*)d_out;
    (void)in_sizes; (void)n_in; (void)out_size;

    cudaFuncSetAttribute(rpe_gate_mma,
                         cudaFuncAttributeMaxDynamicSharedMemorySize, SM_TOT);

    proj_mma<<<384, 256>>>(query, key, Wq, Wk);
    rpe_gate_mma<<<dim3(NK / 64, NQ / 32), 256, SM_TOT>>>(
        qpos, kpos, rpe, w1, b1, w2, b2, out);
}